// round 1
// baseline (speedup 1.0000x reference)
#include <cuda_runtime.h>

// ---------------------------------------------------------------------------
// 3-layer GCN: h=XW; agg[i] = sum_{e:dst=i} norm_e * h[src_e] + dis_i^2*h[i]; +b; tanh
// norm_e = rsqrt(deg_src)*rsqrt(deg_dst), deg = incoming-degree + 1 (self loop).
// Strategy: build CSR (group edges by dst) each launch, gather-side accumulate
// in registers (no float atomics), fuse self-loop+bias+tanh into gather epilogue.
// ---------------------------------------------------------------------------

#define NMAX 100000
#define EMAX 1600000
#define SCAN_B 1024

__device__ int   g_is64;                 // 1 if edge_index is int64, 0 if int32
__device__ int   g_deg[NMAX];            // incoming degree (without self loop)
__device__ int   g_rowptr[NMAX];         // CSR start offsets
__device__ int   g_cursor[NMAX];         // fill cursors
__device__ float g_dis[NMAX];            // deg^-1/2 (incl self loop)
__device__ int2  g_csr[EMAX];            // packed (src, norm-as-bits)
__device__ float g_h[(size_t)NMAX * 64]; // transformed features
__device__ float g_o[(size_t)NMAX * 64]; // layer outputs
__device__ int   g_bsum[SCAN_B];         // scan block sums

// ---- edge index access (dtype-agnostic) -----------------------------------
__device__ __forceinline__ int edge_at(const void* ei, size_t idx) {
    if (g_is64) return (int)((const long long*)ei)[idx];
    return ((const int*)ei)[idx];
}

__global__ void k_detect(const void* ei, int N) {
    if (blockIdx.x == 0 && threadIdx.x == 0) {
        const long long* p = (const long long*)ei;
        int ok = 1;
        for (int i = 0; i < 64; i++) {
            long long v = p[i];
            if (v < 0 || v >= (long long)N) { ok = 0; break; }
        }
        g_is64 = ok;
    }
}

// ---- CSR construction ------------------------------------------------------
__global__ void k_zero2(int N) {
    int i = blockIdx.x * blockDim.x + threadIdx.x;
    if (i < N) { g_deg[i] = 0; g_cursor[i] = 0; }
}

__global__ void k_degree(const void* ei, int E) {
    int e = blockIdx.x * blockDim.x + threadIdx.x;
    if (e >= E) return;
    int d = edge_at(ei, (size_t)E + e);
    atomicAdd(&g_deg[d], 1);
}

__global__ void k_scan1(int N) {
    __shared__ int s[SCAN_B];
    int tid = threadIdx.x;
    int i = blockIdx.x * SCAN_B + tid;
    int v = (i < N) ? g_deg[i] : 0;
    s[tid] = v;
    __syncthreads();
    #pragma unroll
    for (int off = 1; off < SCAN_B; off <<= 1) {
        int t2 = (tid >= off) ? s[tid - off] : 0;
        __syncthreads();
        s[tid] += t2;
        __syncthreads();
    }
    if (i < N) g_rowptr[i] = s[tid] - v;       // exclusive within block
    if (tid == SCAN_B - 1) g_bsum[blockIdx.x] = s[tid];
}

__global__ void k_scan2(int nb) {
    __shared__ int s[SCAN_B];
    int tid = threadIdx.x;
    int v = (tid < nb) ? g_bsum[tid] : 0;
    s[tid] = v;
    __syncthreads();
    #pragma unroll
    for (int off = 1; off < SCAN_B; off <<= 1) {
        int t2 = (tid >= off) ? s[tid - off] : 0;
        __syncthreads();
        s[tid] += t2;
        __syncthreads();
    }
    if (tid < nb) g_bsum[tid] = s[tid] - v;    // exclusive
}

__global__ void k_scan3(int N) {
    int i = blockIdx.x * blockDim.x + threadIdx.x;
    if (i < N) g_rowptr[i] += g_bsum[i >> 10];
}

__global__ void k_dis(int N) {
    int i = blockIdx.x * blockDim.x + threadIdx.x;
    if (i < N) g_dis[i] = rsqrtf((float)(g_deg[i] + 1));
}

__global__ void k_fill(const void* ei, int E) {
    int e = blockIdx.x * blockDim.x + threadIdx.x;
    if (e >= E) return;
    int s = edge_at(ei, e);
    int d = edge_at(ei, (size_t)E + e);
    int pos = atomicAdd(&g_cursor[d], 1);
    float nrm = g_dis[s] * g_dis[d];
    g_csr[g_rowptr[d] + pos] = make_int2(s, __float_as_int(nrm));
}

// ---- dense GEMM: O[N,M] = X[N,K] @ W[K,M]  (no bias here) ------------------
template <int K, int M>
__global__ void k_gemm(const float* __restrict__ X, const float* __restrict__ W,
                       float* __restrict__ O, int N) {
    constexpr int TN = M / 16;
    __shared__ float Ws[K * M];
    int tid = threadIdx.x;
    for (int i = tid; i < K * M; i += 256) Ws[i] = W[i];
    __syncthreads();
    int cg = tid & 15;     // column group (TN cols each)
    int rg = tid >> 4;     // row group (4 rows each) -> 64 rows/block
    int row0 = blockIdx.x * 64 + rg * 4;
    float acc[4][TN];
    #pragma unroll
    for (int r = 0; r < 4; r++)
        #pragma unroll
        for (int t = 0; t < TN; t++) acc[r][t] = 0.f;
    #pragma unroll 4
    for (int k = 0; k < K; k++) {
        float xv[4];
        #pragma unroll
        for (int r = 0; r < 4; r++) {
            int row = row0 + r;
            xv[r] = (row < N) ? X[(size_t)row * K + k] : 0.f;
        }
        #pragma unroll
        for (int t = 0; t < TN; t++) {
            float wv = Ws[k * M + cg * TN + t];
            #pragma unroll
            for (int r = 0; r < 4; r++) acc[r][t] = fmaf(xv[r], wv, acc[r][t]);
        }
    }
    #pragma unroll
    for (int r = 0; r < 4; r++) {
        int row = row0 + r;
        if (row < N) {
            #pragma unroll
            for (int t = 0; t < TN; t++)
                O[(size_t)row * M + cg * TN + t] = acc[r][t];
        }
    }
}

// final projection: O[i] = dot(X[i, 0:32], W3)   (b3 added in gather epilogue)
__global__ void k_gemm_dot(const float* __restrict__ X, const float* __restrict__ W,
                           float* __restrict__ O, int N) {
    __shared__ __align__(16) float w[32];
    if (threadIdx.x < 32) w[threadIdx.x] = W[threadIdx.x];
    __syncthreads();
    int i = blockIdx.x * blockDim.x + threadIdx.x;
    if (i >= N) return;
    const float4* Xv = (const float4*)(X + (size_t)i * 32);
    const float4* Wv = (const float4*)w;
    float acc = 0.f;
    #pragma unroll
    for (int q = 0; q < 8; q++) {
        float4 xv = Xv[q];
        float4 wv = Wv[q];
        acc += xv.x * wv.x + xv.y * wv.y + xv.z * wv.z + xv.w * wv.w;
    }
    O[i] = acc;
}

// ---- gather aggregation (DIM = 64 or 32): L = DIM/4 lanes per node ---------
template <int DIM, bool TANH>
__global__ void k_gather(const float* __restrict__ H, const float* __restrict__ bias,
                         float* __restrict__ O, int N) {
    constexpr int L = DIM / 4;
    int t = blockIdx.x * blockDim.x + threadIdx.x;
    int node = t / L;
    int lane = t % L;
    if (node >= N) return;
    int start = g_rowptr[node];
    int cnt = g_deg[node];
    const float4* Hv = (const float4*)H;
    float4 acc = make_float4(0.f, 0.f, 0.f, 0.f);
    for (int j = 0; j < cnt; j++) {
        int2 p = g_csr[start + j];
        float nrm = __int_as_float(p.y);
        float4 hv = __ldg(&Hv[(size_t)p.x * L + lane]);
        acc.x = fmaf(hv.x, nrm, acc.x);
        acc.y = fmaf(hv.y, nrm, acc.y);
        acc.z = fmaf(hv.z, nrm, acc.z);
        acc.w = fmaf(hv.w, nrm, acc.w);
    }
    float ds = g_dis[node];
    float sw = ds * ds;
    float4 hs = Hv[(size_t)node * L + lane];
    acc.x = fmaf(hs.x, sw, acc.x);
    acc.y = fmaf(hs.y, sw, acc.y);
    acc.z = fmaf(hs.z, sw, acc.z);
    acc.w = fmaf(hs.w, sw, acc.w);
    float4 bv = ((const float4*)bias)[lane];
    acc.x += bv.x; acc.y += bv.y; acc.z += bv.z; acc.w += bv.w;
    if (TANH) {
        acc.x = tanhf(acc.x); acc.y = tanhf(acc.y);
        acc.z = tanhf(acc.z); acc.w = tanhf(acc.w);
    }
    ((float4*)O)[(size_t)node * L + lane] = acc;
}

// scalar final layer: one warp per node, shfl reduce
__global__ void k_gather1(const float* __restrict__ H, const float* __restrict__ b3,
                          float* __restrict__ O, int N) {
    int w = (blockIdx.x * blockDim.x + threadIdx.x) >> 5;
    int lane = threadIdx.x & 31;
    if (w >= N) return;
    int start = g_rowptr[w];
    int cnt = g_deg[w];
    float acc = 0.f;
    for (int j = lane; j < cnt; j += 32) {
        int2 p = g_csr[start + j];
        acc = fmaf(__ldg(&H[p.x]), __int_as_float(p.y), acc);
    }
    #pragma unroll
    for (int off = 16; off; off >>= 1)
        acc += __shfl_down_sync(0xffffffffu, acc, off);
    if (lane == 0) {
        float ds = g_dis[w];
        acc = fmaf(H[w], ds * ds, acc) + b3[0];
        O[w] = acc;
    }
}

// ---------------------------------------------------------------------------
extern "C" void kernel_launch(void* const* d_in, const int* in_sizes, int n_in,
                              void* d_out, int out_size) {
    const float* x  = (const float*)d_in[0];
    const void*  ei = d_in[1];
    const float* W1 = (const float*)d_in[2];
    const float* b1 = (const float*)d_in[3];
    const float* W2 = (const float*)d_in[4];
    const float* b2 = (const float*)d_in[5];
    const float* W3 = (const float*)d_in[6];
    const float* b3 = (const float*)d_in[7];
    float* out = (float*)d_out;

    int N = in_sizes[0] / 64;   // x is [N, 64]
    int E = in_sizes[1] / 2;    // edge_index is [2, E]

    int tb = 256;
    int gN = (N + tb - 1) / tb;
    int gE = (E + tb - 1) / tb;
    int nb = (N + SCAN_B - 1) / SCAN_B;

    // dtype detection + CSR build
    k_detect<<<1, 32>>>(ei, N);
    k_zero2<<<gN, tb>>>(N);
    k_degree<<<gE, tb>>>(ei, E);
    k_scan1<<<nb, SCAN_B>>>(N);
    k_scan2<<<1, SCAN_B>>>(nb);
    k_scan3<<<gN, tb>>>(N);
    k_dis<<<gN, tb>>>(N);
    k_fill<<<gE, tb>>>(ei, E);

    // layer 1: h = x @ W1 [N,64]; gather + self + b1 + tanh -> g_o
    k_gemm<64, 64><<<(N + 63) / 64, 256>>>(x, W1, g_h, N);
    {
        long long nt = (long long)N * 16;
        k_gather<64, true><<<(int)((nt + tb - 1) / tb), tb>>>(g_h, b1, g_o, N);
    }
    // layer 2: h = o1 @ W2 [N,32]; gather + self + b2 + tanh -> g_o
    k_gemm<64, 32><<<(N + 63) / 64, 256>>>(g_o, W2, g_h, N);
    {
        long long nt = (long long)N * 8;
        k_gather<32, true><<<(int)((nt + tb - 1) / tb), tb>>>(g_h, b2, g_o, N);
    }
    // layer 3: h = o2 @ W3 [N,1]; gather + self + b3 -> out
    k_gemm_dot<<<gN, tb>>>(g_o, W3, g_h, N);
    {
        long long nt = (long long)N * 32;
        k_gather1<<<(int)((nt + tb - 1) / tb), tb>>>(g_h, b3, out, N);
    }
}

// round 2
// speedup vs baseline: 1.0657x; 1.0657x over previous
#include <cuda_runtime.h>

// ---------------------------------------------------------------------------
// 3-layer GCN. CSR built per launch (padded to 4-entry multiples so the
// gather loop is branch-free and 4-way unrolled). Gather-side register
// accumulation; self-loop+bias+tanh fused into gather epilogue.
// ---------------------------------------------------------------------------

#define NMAX 100000
#define EMAX 1600000
#define CSRMAX (EMAX + 4 * NMAX)

__device__ int   g_is64;
__device__ int   g_deg[NMAX];
__device__ int   g_rowptr[NMAX];           // padded CSR offsets (multiples of 4)
__device__ int   g_cursor[NMAX];
__device__ float g_dis[NMAX];
__device__ __align__(16) int2 g_csr[CSRMAX];  // (src, norm bits); pads = (0,0)
__device__ float g_h[(size_t)NMAX * 64];
__device__ float g_o[(size_t)NMAX * 64];

__device__ __forceinline__ int edge_at(const void* ei, size_t idx) {
    if (g_is64) return (int)((const long long*)ei)[idx];
    return ((const int*)ei)[idx];
}

// ---- init: zero counters + dtype detect -----------------------------------
__global__ void k_init(const void* ei, int N) {
    int i = blockIdx.x * blockDim.x + threadIdx.x;
    if (i < N) { g_deg[i] = 0; g_cursor[i] = 0; }
    if (i == 0) {
        const long long* p = (const long long*)ei;
        int ok = 1;
        for (int j = 0; j < 64; j++) {
            long long v = p[j];
            if (v < 0 || v >= (long long)N) { ok = 0; break; }
        }
        g_is64 = ok;
    }
}

__global__ void k_degree(const void* ei, int E) {
    int e = blockIdx.x * blockDim.x + threadIdx.x;
    if (e >= E) return;
    atomicAdd(&g_deg[edge_at(ei, (size_t)E + e)], 1);
}

// ---- single-block scan over padded degrees + dis --------------------------
__global__ void k_scan_dis(int N) {
    __shared__ int s[1024];
    int tid = threadIdx.x;
    int C = (N + 1023) >> 10;
    int lo = tid * C;
    int hi = lo + C; if (hi > N) hi = N;
    int sum = 0;
    for (int i = lo; i < hi; i++) sum += (g_deg[i] + 3) & ~3;
    s[tid] = sum;
    __syncthreads();
    #pragma unroll
    for (int off = 1; off < 1024; off <<= 1) {
        int v = (tid >= off) ? s[tid - off] : 0;
        __syncthreads();
        s[tid] += v;
        __syncthreads();
    }
    int run = s[tid] - sum;   // exclusive prefix of this chunk
    for (int i = lo; i < hi; i++) {
        int d = g_deg[i];
        g_rowptr[i] = run;
        run += (d + 3) & ~3;
        g_dis[i] = rsqrtf((float)(d + 1));
    }
}

// ---- fill CSR entries + pad slots ------------------------------------------
__global__ void k_fill(const void* ei, int E, int N) {
    int t = blockIdx.x * blockDim.x + threadIdx.x;
    if (t < E) {
        int s = edge_at(ei, t);
        int d = edge_at(ei, (size_t)E + t);
        int pos = atomicAdd(&g_cursor[d], 1);
        g_csr[g_rowptr[d] + pos] = make_int2(s, __float_as_int(g_dis[s] * g_dis[d]));
    } else if (t < E + N) {
        int n = t - E;
        int st = g_rowptr[n];
        int c = g_deg[n];
        int p = (c + 3) & ~3;
        for (int j = c; j < p; j++) g_csr[st + j] = make_int2(0, 0);
    }
}

// ---- dense GEMM: O[N,M] = X[N,K] @ W[K,M] ----------------------------------
template <int K, int M>
__global__ void k_gemm(const float* __restrict__ X, const float* __restrict__ W,
                       float* __restrict__ O, int N) {
    constexpr int TN = M / 16;
    __shared__ float Ws[K * M];
    int tid = threadIdx.x;
    for (int i = tid; i < K * M; i += 256) Ws[i] = W[i];
    __syncthreads();
    int cg = tid & 15;
    int rg = tid >> 4;
    int row0 = blockIdx.x * 64 + rg * 4;
    float acc[4][TN];
    #pragma unroll
    for (int r = 0; r < 4; r++)
        #pragma unroll
        for (int t = 0; t < TN; t++) acc[r][t] = 0.f;
    #pragma unroll 4
    for (int k = 0; k < K; k++) {
        float xv[4];
        #pragma unroll
        for (int r = 0; r < 4; r++) {
            int row = row0 + r;
            xv[r] = (row < N) ? X[(size_t)row * K + k] : 0.f;
        }
        #pragma unroll
        for (int t = 0; t < TN; t++) {
            float wv = Ws[k * M + cg * TN + t];
            #pragma unroll
            for (int r = 0; r < 4; r++) acc[r][t] = fmaf(xv[r], wv, acc[r][t]);
        }
    }
    #pragma unroll
    for (int r = 0; r < 4; r++) {
        int row = row0 + r;
        if (row < N) {
            #pragma unroll
            for (int t = 0; t < TN; t++)
                O[(size_t)row * M + cg * TN + t] = acc[r][t];
        }
    }
}

__global__ void k_gemm_dot(const float* __restrict__ X, const float* __restrict__ W,
                           float* __restrict__ O, int N) {
    __shared__ __align__(16) float w[32];
    if (threadIdx.x < 32) w[threadIdx.x] = W[threadIdx.x];
    __syncthreads();
    int i = blockIdx.x * blockDim.x + threadIdx.x;
    if (i >= N) return;
    const float4* Xv = (const float4*)(X + (size_t)i * 32);
    const float4* Wv = (const float4*)w;
    float acc = 0.f;
    #pragma unroll
    for (int q = 0; q < 8; q++) {
        float4 xv = Xv[q];
        float4 wv = Wv[q];
        acc += xv.x * wv.x + xv.y * wv.y + xv.z * wv.z + xv.w * wv.w;
    }
    O[i] = acc;
}

// ---- gather: branch-free 4-edge unrolled inner loop ------------------------
template <int DIM, bool TANH>
__global__ void __launch_bounds__(256) k_gather(
        const float* __restrict__ H, const float* __restrict__ bias,
        float* __restrict__ O, int N) {
    constexpr int L = DIM / 4;
    int t = blockIdx.x * blockDim.x + threadIdx.x;
    int node = t / L;
    int lane = t % L;
    if (node >= N) return;
    int start = g_rowptr[node];           // multiple of 4 entries -> 32B aligned
    int pc = (g_deg[node] + 3) >> 2;      // 4-entry groups
    const float4* __restrict__ Hv = (const float4*)H;
    const int4* __restrict__ C4 = (const int4*)(g_csr + start);
    float4 acc = make_float4(0.f, 0.f, 0.f, 0.f);
    for (int it = 0; it < pc; it++) {
        int4 a = __ldg(&C4[2 * it]);
        int4 b = __ldg(&C4[2 * it + 1]);
        float4 h0 = __ldg(&Hv[(size_t)a.x * L + lane]);
        float4 h1 = __ldg(&Hv[(size_t)a.z * L + lane]);
        float4 h2 = __ldg(&Hv[(size_t)b.x * L + lane]);
        float4 h3 = __ldg(&Hv[(size_t)b.z * L + lane]);
        float n0 = __int_as_float(a.y), n1 = __int_as_float(a.w);
        float n2 = __int_as_float(b.y), n3 = __int_as_float(b.w);
        acc.x = fmaf(h3.x, n3, fmaf(h2.x, n2, fmaf(h1.x, n1, fmaf(h0.x, n0, acc.x))));
        acc.y = fmaf(h3.y, n3, fmaf(h2.y, n2, fmaf(h1.y, n1, fmaf(h0.y, n0, acc.y))));
        acc.z = fmaf(h3.z, n3, fmaf(h2.z, n2, fmaf(h1.z, n1, fmaf(h0.z, n0, acc.z))));
        acc.w = fmaf(h3.w, n3, fmaf(h2.w, n2, fmaf(h1.w, n1, fmaf(h0.w, n0, acc.w))));
    }
    float ds = g_dis[node];
    float sw = ds * ds;
    float4 hs = Hv[(size_t)node * L + lane];
    acc.x = fmaf(hs.x, sw, acc.x);
    acc.y = fmaf(hs.y, sw, acc.y);
    acc.z = fmaf(hs.z, sw, acc.z);
    acc.w = fmaf(hs.w, sw, acc.w);
    float4 bv = ((const float4*)bias)[lane];
    acc.x += bv.x; acc.y += bv.y; acc.z += bv.z; acc.w += bv.w;
    if (TANH) {
        acc.x = tanhf(acc.x); acc.y = tanhf(acc.y);
        acc.z = tanhf(acc.z); acc.w = tanhf(acc.w);
    }
    ((float4*)O)[(size_t)node * L + lane] = acc;
}

// scalar final layer: one warp per node
__global__ void k_gather1(const float* __restrict__ H, const float* __restrict__ b3,
                          float* __restrict__ O, int N) {
    int w = (blockIdx.x * blockDim.x + threadIdx.x) >> 5;
    int lane = threadIdx.x & 31;
    if (w >= N) return;
    int start = g_rowptr[w];
    int cnt = g_deg[w];
    float acc = 0.f;
    for (int j = lane; j < cnt; j += 32) {
        int2 p = __ldg(&g_csr[start + j]);
        acc = fmaf(__ldg(&H[p.x]), __int_as_float(p.y), acc);
    }
    #pragma unroll
    for (int off = 16; off; off >>= 1)
        acc += __shfl_down_sync(0xffffffffu, acc, off);
    if (lane == 0) {
        float ds = g_dis[w];
        O[w] = fmaf(H[w], ds * ds, acc) + b3[0];
    }
}

// ---------------------------------------------------------------------------
extern "C" void kernel_launch(void* const* d_in, const int* in_sizes, int n_in,
                              void* d_out, int out_size) {
    const float* x  = (const float*)d_in[0];
    const void*  ei = d_in[1];
    const float* W1 = (const float*)d_in[2];
    const float* b1 = (const float*)d_in[3];
    const float* W2 = (const float*)d_in[4];
    const float* b2 = (const float*)d_in[5];
    const float* W3 = (const float*)d_in[6];
    const float* b3 = (const float*)d_in[7];
    float* out = (float*)d_out;

    int N = in_sizes[0] / 64;
    int E = in_sizes[1] / 2;

    int tb = 256;
    int gN = (N + tb - 1) / tb;
    int gE = (E + tb - 1) / tb;
    int gEN = (E + N + tb - 1) / tb;

    k_init<<<gN, tb>>>(ei, N);
    k_degree<<<gE, tb>>>(ei, E);
    k_scan_dis<<<1, 1024>>>(N);
    k_fill<<<gEN, tb>>>(ei, E, N);

    k_gemm<64, 64><<<(N + 63) / 64, 256>>>(x, W1, g_h, N);
    {
        long long nt = (long long)N * 16;
        k_gather<64, true><<<(int)((nt + tb - 1) / tb), tb>>>(g_h, b1, g_o, N);
    }
    k_gemm<64, 32><<<(N + 63) / 64, 256>>>(g_o, W2, g_h, N);
    {
        long long nt = (long long)N * 8;
        k_gather<32, true><<<(int)((nt + tb - 1) / tb), tb>>>(g_h, b2, g_o, N);
    }
    k_gemm_dot<<<gN, tb>>>(g_o, W3, g_h, N);
    {
        long long nt = (long long)N * 32;
        k_gather1<<<(int)((nt + tb - 1) / tb), tb>>>(g_h, b3, out, N);
    }
}

// round 3
// speedup vs baseline: 20.2244x; 18.9773x over previous
#include <cuda_runtime.h>

// ---------------------------------------------------------------------------
// 3-layer GCN as ONE persistent megakernel: CSR build (padded to 4-entry
// groups), 3x (GEMM -> gather+self+bias[+tanh]) with device-wide spin
// barriers between phases. 592 CTAs x 256 threads, co-residency forced via
// __launch_bounds__(256,4).
// ---------------------------------------------------------------------------

#define NMAX 100000
#define EMAX 1600000
#define CSRMAX (EMAX + 4 * NMAX)
#define NB  592
#define TPB 256
#define NTH (NB * TPB)

__device__ unsigned g_bar;               // global barrier counter (reset at end)
__device__ int   g_is64;
__device__ int   g_deg[NMAX];
__device__ int   g_rowptr[NMAX];
__device__ int   g_cursor[NMAX];
__device__ float g_dis[NMAX];
__device__ __align__(16) int2 g_csr[CSRMAX];
__device__ float g_h[(size_t)NMAX * 64];
__device__ float g_o[(size_t)NMAX * 64];
__device__ int   g_bsums[NB];

struct SM {
    float w[4096];   // weight staging (16KB max)
    int   s[TPB];    // scan buffer
};

__device__ __forceinline__ void gsync(unsigned target) {
    __syncthreads();
    if (threadIdx.x == 0) {
        __threadfence();
        atomicAdd(&g_bar, 1u);
        while (*((volatile unsigned*)&g_bar) < target) { }
    }
    __syncthreads();
}

__device__ __forceinline__ int block_scan_incl(int v, int* s) {
    int t = s != nullptr ? threadIdx.x : 0;
    s[t] = v;
    __syncthreads();
    #pragma unroll
    for (int off = 1; off < TPB; off <<= 1) {
        int u = (t >= off) ? s[t - off] : 0;
        __syncthreads();
        s[t] += u;
        __syncthreads();
    }
    int r = s[t];
    __syncthreads();
    return r;
}

__device__ __forceinline__ int edge_at(const void* ei, size_t idx, int is64) {
    if (is64) return (int)((const long long*)ei)[idx];
    return ((const int*)ei)[idx];
}

// ---- GEMM phase: O[N,M] = X[N,K] @ W[K,M] ----------------------------------
template <int K, int M>
__device__ void gemm_phase(const float* __restrict__ X, const float* __restrict__ W,
                           float* __restrict__ O, int N, SM* sm) {
    constexpr int TN = M / 16;
    for (int i = threadIdx.x; i < K * M; i += TPB) sm->w[i] = W[i];
    __syncthreads();
    int cg = threadIdx.x & 15;
    int rg = threadIdx.x >> 4;
    int tiles = (N + 63) >> 6;
    for (int tile = blockIdx.x; tile < tiles; tile += NB) {
        int row0 = tile * 64 + rg * 4;
        float acc[4][TN];
        #pragma unroll
        for (int r = 0; r < 4; r++)
            #pragma unroll
            for (int t = 0; t < TN; t++) acc[r][t] = 0.f;
        #pragma unroll 4
        for (int k = 0; k < K; k++) {
            float xv[4];
            #pragma unroll
            for (int r = 0; r < 4; r++) {
                int row = row0 + r;
                xv[r] = (row < N) ? X[(size_t)row * K + k] : 0.f;
            }
            #pragma unroll
            for (int t = 0; t < TN; t++) {
                float wv = sm->w[k * M + cg * TN + t];
                #pragma unroll
                for (int r = 0; r < 4; r++) acc[r][t] = fmaf(xv[r], wv, acc[r][t]);
            }
        }
        #pragma unroll
        for (int r = 0; r < 4; r++) {
            int row = row0 + r;
            if (row < N) {
                #pragma unroll
                for (int t = 0; t < TN; t++)
                    O[(size_t)row * M + cg * TN + t] = acc[r][t];
            }
        }
    }
    __syncthreads();
}

// ---- gather phase: 4-edge unrolled, branch-free ----------------------------
template <int DIM, bool TANH>
__device__ void gather_phase(const float* __restrict__ H, const float* __restrict__ bias,
                             float* __restrict__ O, int N) {
    constexpr int L = DIM / 4;           // float4 lanes per node
    constexpr int SH = (DIM == 64) ? 4 : 3;
    const float4* __restrict__ Hv = (const float4*)H;
    long long items = (long long)N * L;
    for (long long it = blockIdx.x * TPB + threadIdx.x; it < items; it += NTH) {
        int node = (int)(it >> SH);
        int lane = (int)(it & (L - 1));
        int start = g_rowptr[node];
        int pc = (g_deg[node] + 3) >> 2;
        const int4* __restrict__ C4 = (const int4*)(g_csr + start);
        float4 acc = make_float4(0.f, 0.f, 0.f, 0.f);
        for (int j = 0; j < pc; j++) {
            int4 a = __ldg(&C4[2 * j]);
            int4 b = __ldg(&C4[2 * j + 1]);
            float4 h0 = __ldg(&Hv[(size_t)a.x * L + lane]);
            float4 h1 = __ldg(&Hv[(size_t)a.z * L + lane]);
            float4 h2 = __ldg(&Hv[(size_t)b.x * L + lane]);
            float4 h3 = __ldg(&Hv[(size_t)b.z * L + lane]);
            float n0 = __int_as_float(a.y), n1 = __int_as_float(a.w);
            float n2 = __int_as_float(b.y), n3 = __int_as_float(b.w);
            acc.x = fmaf(h3.x, n3, fmaf(h2.x, n2, fmaf(h1.x, n1, fmaf(h0.x, n0, acc.x))));
            acc.y = fmaf(h3.y, n3, fmaf(h2.y, n2, fmaf(h1.y, n1, fmaf(h0.y, n0, acc.y))));
            acc.z = fmaf(h3.z, n3, fmaf(h2.z, n2, fmaf(h1.z, n1, fmaf(h0.z, n0, acc.z))));
            acc.w = fmaf(h3.w, n3, fmaf(h2.w, n2, fmaf(h1.w, n1, fmaf(h0.w, n0, acc.w))));
        }
        float ds = g_dis[node];
        float sw = ds * ds;
        float4 hs = __ldg(&Hv[(size_t)node * L + lane]);
        acc.x = fmaf(hs.x, sw, acc.x);
        acc.y = fmaf(hs.y, sw, acc.y);
        acc.z = fmaf(hs.z, sw, acc.z);
        acc.w = fmaf(hs.w, sw, acc.w);
        float4 bv = __ldg(&((const float4*)bias)[lane]);
        acc.x += bv.x; acc.y += bv.y; acc.z += bv.z; acc.w += bv.w;
        if (TANH) {
            acc.x = tanhf(acc.x); acc.y = tanhf(acc.y);
            acc.z = tanhf(acc.z); acc.w = tanhf(acc.w);
        }
        ((float4*)O)[(size_t)node * L + lane] = acc;
    }
}

// ---------------------------------------------------------------------------
__global__ void __launch_bounds__(TPB, 4) k_mega(
        const float* __restrict__ x, const void* __restrict__ ei,
        const float* __restrict__ W1, const float* __restrict__ b1,
        const float* __restrict__ W2, const float* __restrict__ b2,
        const float* __restrict__ W3, const float* __restrict__ b3,
        float* __restrict__ out, int N, int E) {
    __shared__ SM sm;
    int gtid = blockIdx.x * TPB + threadIdx.x;

    // P0: zero counters + dtype detect (warp-parallel)
    for (int i = gtid; i < N; i += NTH) { g_deg[i] = 0; g_cursor[i] = 0; }
    if (blockIdx.x == 0 && threadIdx.x < 32) {
        const long long* p = (const long long*)ei;
        long long v0 = p[threadIdx.x], v1 = p[32 + threadIdx.x];
        int ok = (v0 >= 0 && v0 < (long long)N && v1 >= 0 && v1 < (long long)N);
        unsigned m = __ballot_sync(0xffffffffu, ok);
        if (threadIdx.x == 0) g_is64 = (m == 0xffffffffu);
    }
    gsync(1u * NB);
    int is64 = g_is64;

    // P1: degree histogram
    for (int e = gtid; e < E; e += NTH)
        atomicAdd(&g_deg[edge_at(ei, (size_t)E + e, is64)], 1);
    gsync(2u * NB);

    // P2a: per-block padded-degree sums + dis; keep exclusive prefix in reg
    int CN = (N + NB - 1) / NB;             // nodes per block (<= TPB)
    int base = blockIdx.x * CN;
    int cnt = N - base; if (cnt > CN) cnt = CN; if (cnt < 0) cnt = 0;
    int pd = 0;
    if (threadIdx.x < cnt) {
        int d = g_deg[base + threadIdx.x];
        pd = (d + 3) & ~3;
        g_dis[base + threadIdx.x] = rsqrtf((float)(d + 1));
    }
    int incl = block_scan_incl(pd, sm.s);
    int excl = incl - pd;
    if (threadIdx.x == TPB - 1) g_bsums[blockIdx.x] = incl;  // block total
    gsync(3u * NB);

    // P2b: block 0 exclusive-scans block sums
    if (blockIdx.x == 0) {
        const int G = (NB + TPB - 1) / TPB;   // values per thread
        int v[G]; int lsum = 0;
        #pragma unroll
        for (int j = 0; j < G; j++) {
            int idx = threadIdx.x * G + j;
            int val = (idx < NB) ? g_bsums[idx] : 0;
            v[j] = lsum; lsum += val;
        }
        int li = block_scan_incl(lsum, sm.s);
        int le = li - lsum;
        #pragma unroll
        for (int j = 0; j < G; j++) {
            int idx = threadIdx.x * G + j;
            if (idx < NB) g_bsums[idx] = le + v[j];
        }
    }
    gsync(4u * NB);

    // P2c: write padded rowptr
    if (threadIdx.x < cnt) g_rowptr[base + threadIdx.x] = g_bsums[blockIdx.x] + excl;
    gsync(5u * NB);

    // P3: fill CSR + pad slots
    for (int e = gtid; e < E; e += NTH) {
        int s = edge_at(ei, e, is64);
        int d = edge_at(ei, (size_t)E + e, is64);
        int pos = atomicAdd(&g_cursor[d], 1);
        g_csr[g_rowptr[d] + pos] = make_int2(s, __float_as_int(g_dis[s] * g_dis[d]));
    }
    for (int i = gtid; i < N; i += NTH) {
        int st = g_rowptr[i];
        int c = g_deg[i];
        int p = (c + 3) & ~3;
        for (int j = c; j < p; j++) g_csr[st + j] = make_int2(0, 0);
    }
    gsync(6u * NB);

    // P4..P5: layer 1
    gemm_phase<64, 64>(x, W1, g_h, N, &sm);
    gsync(7u * NB);
    gather_phase<64, true>(g_h, b1, g_o, N);
    gsync(8u * NB);

    // P6..P7: layer 2
    gemm_phase<64, 32>(g_o, W2, g_h, N, &sm);
    gsync(9u * NB);
    gather_phase<32, true>(g_h, b2, g_o, N);
    gsync(10u * NB);

    // P8: final projection h = o2 . W3  (scalar per node)
    for (int i = threadIdx.x; i < 32; i += TPB) sm.w[i] = W3[i];
    __syncthreads();
    {
        const float4* Wv = (const float4*)sm.w;
        for (int i = gtid; i < N; i += NTH) {
            const float4* Xv = (const float4*)(g_o + (size_t)i * 32);
            float acc = 0.f;
            #pragma unroll
            for (int q = 0; q < 8; q++) {
                float4 xv = __ldg(&Xv[q]);
                float4 wv = Wv[q];
                acc += xv.x * wv.x + xv.y * wv.y + xv.z * wv.z + xv.w * wv.w;
            }
            g_h[i] = acc;
        }
    }
    gsync(11u * NB);

    // P9: scalar gather (one warp per node), then final arrive + reset
    {
        float bb = b3[0];
        int wg = gtid >> 5;
        int lane = threadIdx.x & 31;
        for (int n = wg; n < N; n += (NTH >> 5)) {
            int start = g_rowptr[n];
            int c = g_deg[n];
            float acc = 0.f;
            for (int j = lane; j < c; j += 32) {
                int2 p = __ldg(&g_csr[start + j]);
                acc = fmaf(__ldg(&g_h[p.x]), __int_as_float(p.y), acc);
            }
            #pragma unroll
            for (int off = 16; off; off >>= 1)
                acc += __shfl_down_sync(0xffffffffu, acc, off);
            if (lane == 0) {
                float ds = g_dis[n];
                out[n] = fmaf(g_h[n], ds * ds, acc) + bb;
            }
        }
    }

    // final arrival: last CTA resets barrier for next graph replay
    __syncthreads();
    if (threadIdx.x == 0) {
        __threadfence();
        unsigned v = atomicAdd(&g_bar, 1u);
        if (v == 12u * NB - 1u) g_bar = 0u;
    }
}

// ---------------------------------------------------------------------------
extern "C" void kernel_launch(void* const* d_in, const int* in_sizes, int n_in,
                              void* d_out, int out_size) {
    const float* x  = (const float*)d_in[0];
    const void*  ei = d_in[1];
    const float* W1 = (const float*)d_in[2];
    const float* b1 = (const float*)d_in[3];
    const float* W2 = (const float*)d_in[4];
    const float* b2 = (const float*)d_in[5];
    const float* W3 = (const float*)d_in[6];
    const float* b3 = (const float*)d_in[7];
    float* out = (float*)d_out;

    int N = in_sizes[0] / 64;
    int E = in_sizes[1] / 2;

    k_mega<<<NB, TPB>>>(x, ei, W1, b1, W2, b2, W3, b3, out, N, E);
}

// round 4
// speedup vs baseline: 22.7914x; 1.1269x over previous
#include <cuda_runtime.h>

// ---------------------------------------------------------------------------
// 3-layer GCN persistent megakernel, round 4:
//  - atomic bump-allocated CSR offsets (no prefix scan, fewer barriers)
//  - vectorized GEMM (float4 LDG/LDS)
//  - tanh.approx.f32 (MUFU.TANH)
//  - nanosleep backoff in global spin barrier
// ---------------------------------------------------------------------------

#define NMAX 100000
#define EMAX 1600000
#define CSRMAX (EMAX + 4 * NMAX)
#define NB  592
#define TPB 256
#define NTH (NB * TPB)

__device__ unsigned g_bar;
__device__ int   g_alloc;
__device__ int   g_is64;
__device__ int   g_deg[NMAX];
__device__ int   g_rowptr[NMAX];
__device__ int   g_cursor[NMAX];
__device__ float g_dis[NMAX];
__device__ __align__(16) int2 g_csr[CSRMAX];
__device__ float g_h[(size_t)NMAX * 64];
__device__ float g_o[(size_t)NMAX * 64];

struct SM {
    __align__(16) float w[4096];
};

__device__ __forceinline__ float fast_tanh(float x) {
    float y;
    asm("tanh.approx.f32 %0, %1;" : "=f"(y) : "f"(x));
    return y;
}

__device__ __forceinline__ void gsync(unsigned target) {
    __syncthreads();
    if (threadIdx.x == 0) {
        __threadfence();
        atomicAdd(&g_bar, 1u);
        while (*((volatile unsigned*)&g_bar) < target) __nanosleep(128);
    }
    __syncthreads();
}

__device__ __forceinline__ int edge_at(const void* ei, size_t idx, int is64) {
    if (is64) return (int)((const long long*)ei)[idx];
    return ((const int*)ei)[idx];
}

// ---- GEMM phase: O[N,M] = X[N,K] @ W[K,M], vectorized ----------------------
template <int K, int M>
__device__ void gemm_phase(const float* __restrict__ X, const float* __restrict__ W,
                           float* __restrict__ O, int N, SM* sm) {
    constexpr int TN = M / 16;            // 4 (M=64) or 2 (M=32)
    for (int i = threadIdx.x; i < K * M; i += TPB) sm->w[i] = W[i];
    __syncthreads();
    int cg = threadIdx.x & 15;
    int rg = threadIdx.x >> 4;
    int tiles = (N + 63) >> 6;
    const float4* __restrict__ X4 = (const float4*)X;
    for (int tile = blockIdx.x; tile < tiles; tile += NB) {
        int row0 = tile * 64 + rg * 4;
        bool full = (row0 + 3 < N);
        float acc[4][TN];
        #pragma unroll
        for (int r = 0; r < 4; r++)
            #pragma unroll
            for (int t = 0; t < TN; t++) acc[r][t] = 0.f;
        #pragma unroll 4
        for (int k4 = 0; k4 < K / 4; k4++) {
            float4 xv[4];
            #pragma unroll
            for (int r = 0; r < 4; r++) {
                int row = row0 + r;
                if (full || row < N) xv[r] = __ldg(&X4[(size_t)row * (K / 4) + k4]);
                else xv[r] = make_float4(0.f, 0.f, 0.f, 0.f);
            }
            #pragma unroll
            for (int kk = 0; kk < 4; kk++) {
                int k = k4 * 4 + kk;
                float wv[TN];
                if (TN == 4) {
                    float4 wq = ((const float4*)sm->w)[k * (M / 4) + cg];
                    wv[0] = wq.x; wv[1] = wq.y; wv[2] = wq.z; wv[3] = wq.w;
                } else {
                    float2 wq = ((const float2*)sm->w)[k * (M / 2) + cg];
                    wv[0] = wq.x; wv[1] = wq.y;
                }
                float xs[4] = { kk == 0 ? xv[0].x : kk == 1 ? xv[0].y : kk == 2 ? xv[0].z : xv[0].w,
                                kk == 0 ? xv[1].x : kk == 1 ? xv[1].y : kk == 2 ? xv[1].z : xv[1].w,
                                kk == 0 ? xv[2].x : kk == 1 ? xv[2].y : kk == 2 ? xv[2].z : xv[2].w,
                                kk == 0 ? xv[3].x : kk == 1 ? xv[3].y : kk == 2 ? xv[3].z : xv[3].w };
                #pragma unroll
                for (int t = 0; t < TN; t++)
                    #pragma unroll
                    for (int r = 0; r < 4; r++)
                        acc[r][t] = fmaf(xs[r], wv[t], acc[r][t]);
            }
        }
        #pragma unroll
        for (int r = 0; r < 4; r++) {
            int row = row0 + r;
            if (row < N) {
                #pragma unroll
                for (int t = 0; t < TN; t++)
                    O[(size_t)row * M + cg * TN + t] = acc[r][t];
            }
        }
    }
    __syncthreads();
}

// ---- gather phase ----------------------------------------------------------
template <int DIM, bool TANH>
__device__ void gather_phase(const float* __restrict__ H, const float* __restrict__ bias,
                             float* __restrict__ O, int N) {
    constexpr int L = DIM / 4;
    constexpr int SH = (DIM == 64) ? 4 : 3;
    const float4* __restrict__ Hv = (const float4*)H;
    long long items = (long long)N * L;
    for (long long it = blockIdx.x * TPB + threadIdx.x; it < items; it += NTH) {
        int node = (int)(it >> SH);
        int lane = (int)(it & (L - 1));
        int start = g_rowptr[node];
        int pc = (g_deg[node] + 3) >> 2;
        const int4* __restrict__ C4 = (const int4*)(g_csr + start);
        float4 acc = make_float4(0.f, 0.f, 0.f, 0.f);
        for (int j = 0; j < pc; j++) {
            int4 a = __ldg(&C4[2 * j]);
            int4 b = __ldg(&C4[2 * j + 1]);
            float4 h0 = __ldg(&Hv[(size_t)a.x * L + lane]);
            float4 h1 = __ldg(&Hv[(size_t)a.z * L + lane]);
            float4 h2 = __ldg(&Hv[(size_t)b.x * L + lane]);
            float4 h3 = __ldg(&Hv[(size_t)b.z * L + lane]);
            float n0 = __int_as_float(a.y), n1 = __int_as_float(a.w);
            float n2 = __int_as_float(b.y), n3 = __int_as_float(b.w);
            acc.x = fmaf(h3.x, n3, fmaf(h2.x, n2, fmaf(h1.x, n1, fmaf(h0.x, n0, acc.x))));
            acc.y = fmaf(h3.y, n3, fmaf(h2.y, n2, fmaf(h1.y, n1, fmaf(h0.y, n0, acc.y))));
            acc.z = fmaf(h3.z, n3, fmaf(h2.z, n2, fmaf(h1.z, n1, fmaf(h0.z, n0, acc.z))));
            acc.w = fmaf(h3.w, n3, fmaf(h2.w, n2, fmaf(h1.w, n1, fmaf(h0.w, n0, acc.w))));
        }
        float ds = g_dis[node];
        float sw = ds * ds;
        float4 hs = __ldg(&Hv[(size_t)node * L + lane]);
        acc.x = fmaf(hs.x, sw, acc.x);
        acc.y = fmaf(hs.y, sw, acc.y);
        acc.z = fmaf(hs.z, sw, acc.z);
        acc.w = fmaf(hs.w, sw, acc.w);
        float4 bv = __ldg(&((const float4*)bias)[lane]);
        acc.x += bv.x; acc.y += bv.y; acc.z += bv.z; acc.w += bv.w;
        if (TANH) {
            acc.x = fast_tanh(acc.x); acc.y = fast_tanh(acc.y);
            acc.z = fast_tanh(acc.z); acc.w = fast_tanh(acc.w);
        }
        ((float4*)O)[(size_t)node * L + lane] = acc;
    }
}

// ---------------------------------------------------------------------------
__global__ void __launch_bounds__(TPB, 4) k_mega(
        const float* __restrict__ x, const void* __restrict__ ei,
        const float* __restrict__ W1, const float* __restrict__ b1,
        const float* __restrict__ W2, const float* __restrict__ b2,
        const float* __restrict__ W3, const float* __restrict__ b3,
        float* __restrict__ out, int N, int E) {
    __shared__ SM sm;
    int gtid = blockIdx.x * TPB + threadIdx.x;

    // P0: zero counters, reset allocator, dtype detect
    for (int i = gtid; i < N; i += NTH) { g_deg[i] = 0; g_cursor[i] = 0; }
    if (gtid == 0) g_alloc = 0;
    if (blockIdx.x == 0 && threadIdx.x < 32) {
        const long long* p = (const long long*)ei;
        long long v0 = p[threadIdx.x], v1 = p[32 + threadIdx.x];
        int ok = (v0 >= 0 && v0 < (long long)N && v1 >= 0 && v1 < (long long)N);
        unsigned m = __ballot_sync(0xffffffffu, ok);
        if (threadIdx.x == 0) g_is64 = (m == 0xffffffffu);
    }
    gsync(1u * NB);
    int is64 = g_is64;

    // P1: degree histogram
    for (int e = gtid; e < E; e += NTH)
        atomicAdd(&g_deg[edge_at(ei, (size_t)E + e, is64)], 1);
    gsync(2u * NB);

    // P2: bump-allocate padded CSR offsets + dis (order-free)
    for (int i = gtid; i < N; i += NTH) {
        int d = g_deg[i];
        g_rowptr[i] = atomicAdd(&g_alloc, (d + 3) & ~3);
        g_dis[i] = rsqrtf((float)(d + 1));
    }
    gsync(3u * NB);

    // P3: fill CSR + pad slots
    for (int e = gtid; e < E; e += NTH) {
        int s = edge_at(ei, e, is64);
        int d = edge_at(ei, (size_t)E + e, is64);
        int pos = atomicAdd(&g_cursor[d], 1);
        g_csr[g_rowptr[d] + pos] = make_int2(s, __float_as_int(g_dis[s] * g_dis[d]));
    }
    for (int i = gtid; i < N; i += NTH) {
        int st = g_rowptr[i];
        int c = g_deg[i];
        int p = (c + 3) & ~3;
        for (int j = c; j < p; j++) g_csr[st + j] = make_int2(0, 0);
    }
    gsync(4u * NB);

    // layer 1
    gemm_phase<64, 64>(x, W1, g_h, N, &sm);
    gsync(5u * NB);
    gather_phase<64, true>(g_h, b1, g_o, N);
    gsync(6u * NB);

    // layer 2
    gemm_phase<64, 32>(g_o, W2, g_h, N, &sm);
    gsync(7u * NB);
    gather_phase<32, true>(g_h, b2, g_o, N);
    gsync(8u * NB);

    // final projection h = o2 . W3
    for (int i = threadIdx.x; i < 32; i += TPB) sm.w[i] = W3[i];
    __syncthreads();
    {
        const float4* Wv = (const float4*)sm.w;
        for (int i = gtid; i < N; i += NTH) {
            const float4* Xv = (const float4*)(g_o + (size_t)i * 32);
            float acc = 0.f;
            #pragma unroll
            for (int q = 0; q < 8; q++) {
                float4 xv = __ldg(&Xv[q]);
                float4 wv = Wv[q];
                acc += xv.x * wv.x + xv.y * wv.y + xv.z * wv.z + xv.w * wv.w;
            }
            g_h[i] = acc;
        }
    }
    gsync(9u * NB);

    // final scalar gather: one warp per node
    {
        float bb = b3[0];
        int wg = gtid >> 5;
        int lane = threadIdx.x & 31;
        for (int n = wg; n < N; n += (NTH >> 5)) {
            int start = g_rowptr[n];
            int c = g_deg[n];
            float acc = 0.f;
            for (int j = lane; j < c; j += 32) {
                int2 p = __ldg(&g_csr[start + j]);
                acc = fmaf(__ldg(&g_h[p.x]), __int_as_float(p.y), acc);
            }
            #pragma unroll
            for (int off = 16; off; off >>= 1)
                acc += __shfl_down_sync(0xffffffffu, acc, off);
            if (lane == 0) {
                float ds = g_dis[n];
                out[n] = fmaf(g_h[n], ds * ds, acc) + bb;
            }
        }
    }

    // final arrival: last CTA resets barrier for next graph replay
    __syncthreads();
    if (threadIdx.x == 0) {
        __threadfence();
        unsigned v = atomicAdd(&g_bar, 1u);
        if (v == 10u * NB - 1u) g_bar = 0u;
    }
}

// ---------------------------------------------------------------------------
extern "C" void kernel_launch(void* const* d_in, const int* in_sizes, int n_in,
                              void* d_out, int out_size) {
    const float* x  = (const float*)d_in[0];
    const void*  ei = d_in[1];
    const float* W1 = (const float*)d_in[2];
    const float* b1 = (const float*)d_in[3];
    const float* W2 = (const float*)d_in[4];
    const float* b2 = (const float*)d_in[5];
    const float* W3 = (const float*)d_in[6];
    const float* b3 = (const float*)d_in[7];
    float* out = (float*)d_out;

    int N = in_sizes[0] / 64;
    int E = in_sizes[1] / 2;

    k_mega<<<NB, TPB>>>(x, ei, W1, b1, W2, b2, W3, b3, out, N, E);
}

// round 5
// speedup vs baseline: 24.3953x; 1.0704x over previous
#include <cuda_runtime.h>

// ---------------------------------------------------------------------------
// 3-layer GCN persistent megakernel, round 5:
//  - __launch_bounds__(256,5): 1280 thr/SM (51-reg cap) for latency hiding
//  - 6 global barriers (was 10): GEMM1 fused with degree phase, projection
//    fused into gather2 epilogue (width-8 shuffle), deferred zeroing
//    (cursor zeroed in gather1, deg zeroed in gather3, alloc reset at exit)
// ---------------------------------------------------------------------------

#define NMAX 100000
#define EMAX 1600000
#define CSRMAX (EMAX + 4 * NMAX)
#define NB  740          // 148 SMs x 5 CTAs
#define TPB 256
#define NTH (NB * TPB)

__device__ unsigned g_bar;     // zero-init; restored to 0 at exit
__device__ int   g_alloc;      // zero-init; restored to 0 at exit
__device__ int   g_is64;
__device__ int   g_deg[NMAX];     // zeroed by previous run's gather3
__device__ int   g_rowptr[NMAX];
__device__ int   g_cursor[NMAX];  // zeroed by previous run's gather1 phase
__device__ float g_dis[NMAX];
__device__ __align__(16) int2 g_csr[CSRMAX];
__device__ float g_h[(size_t)NMAX * 64];
__device__ float g_o[(size_t)NMAX * 64];

struct SM {
    __align__(16) float w[4096];
};

__device__ __forceinline__ float fast_tanh(float x) {
    float y;
    asm("tanh.approx.f32 %0, %1;" : "=f"(y) : "f"(x));
    return y;
}

__device__ __forceinline__ void gsync(unsigned target) {
    __syncthreads();
    if (threadIdx.x == 0) {
        __threadfence();
        atomicAdd(&g_bar, 1u);
        while (*((volatile unsigned*)&g_bar) < target) __nanosleep(64);
    }
    __syncthreads();
}

__device__ __forceinline__ int edge_at(const void* ei, size_t idx, int is64) {
    if (is64) return (int)((const long long*)ei)[idx];
    return ((const int*)ei)[idx];
}

// ---- GEMM: O[N,M] = X[N,K] @ W[K,M], vectorized ----------------------------
template <int K, int M>
__device__ void gemm_phase(const float* __restrict__ X, const float* __restrict__ W,
                           float* __restrict__ O, int N, SM* sm) {
    constexpr int TN = M / 16;
    for (int i = threadIdx.x; i < K * M; i += TPB) sm->w[i] = W[i];
    __syncthreads();
    int cg = threadIdx.x & 15;
    int rg = threadIdx.x >> 4;
    int tiles = (N + 63) >> 6;
    const float4* __restrict__ X4 = (const float4*)X;
    for (int tile = blockIdx.x; tile < tiles; tile += NB) {
        int row0 = tile * 64 + rg * 4;
        bool full = (row0 + 3 < N);
        float acc[4][TN];
        #pragma unroll
        for (int r = 0; r < 4; r++)
            #pragma unroll
            for (int t = 0; t < TN; t++) acc[r][t] = 0.f;
        #pragma unroll 2
        for (int k4 = 0; k4 < K / 4; k4++) {
            float4 xv[4];
            #pragma unroll
            for (int r = 0; r < 4; r++) {
                int row = row0 + r;
                if (full || row < N) xv[r] = __ldg(&X4[(size_t)row * (K / 4) + k4]);
                else xv[r] = make_float4(0.f, 0.f, 0.f, 0.f);
            }
            #pragma unroll
            for (int kk = 0; kk < 4; kk++) {
                int k = k4 * 4 + kk;
                float wv[TN];
                if (TN == 4) {
                    float4 wq = ((const float4*)sm->w)[k * (M / 4) + cg];
                    wv[0] = wq.x; wv[1] = wq.y; wv[2] = wq.z; wv[3] = wq.w;
                } else {
                    float2 wq = ((const float2*)sm->w)[k * (M / 2) + cg];
                    wv[0] = wq.x; wv[1] = wq.y;
                }
                float xs[4] = { kk == 0 ? xv[0].x : kk == 1 ? xv[0].y : kk == 2 ? xv[0].z : xv[0].w,
                                kk == 0 ? xv[1].x : kk == 1 ? xv[1].y : kk == 2 ? xv[1].z : xv[1].w,
                                kk == 0 ? xv[2].x : kk == 1 ? xv[2].y : kk == 2 ? xv[2].z : xv[2].w,
                                kk == 0 ? xv[3].x : kk == 1 ? xv[3].y : kk == 2 ? xv[3].z : xv[3].w };
                #pragma unroll
                for (int t = 0; t < TN; t++)
                    #pragma unroll
                    for (int r = 0; r < 4; r++)
                        acc[r][t] = fmaf(xs[r], wv[t], acc[r][t]);
            }
        }
        #pragma unroll
        for (int r = 0; r < 4; r++) {
            int row = row0 + r;
            if (row < N) {
                #pragma unroll
                for (int t = 0; t < TN; t++)
                    O[(size_t)row * M + cg * TN + t] = acc[r][t];
            }
        }
    }
    __syncthreads();
}

// ---- gather core (per item = node x float4-lane) ---------------------------
template <int L>
__device__ __forceinline__ float4 gather_acc(const float4* __restrict__ Hv,
                                             int node, int lane) {
    int start = g_rowptr[node];
    int pc = (g_deg[node] + 3) >> 2;
    const int4* __restrict__ C4 = (const int4*)(g_csr + start);
    float4 acc = make_float4(0.f, 0.f, 0.f, 0.f);
    for (int j = 0; j < pc; j++) {
        int4 a = __ldg(&C4[2 * j]);
        int4 b = __ldg(&C4[2 * j + 1]);
        float4 h0 = __ldg(&Hv[(size_t)a.x * L + lane]);
        float4 h1 = __ldg(&Hv[(size_t)a.z * L + lane]);
        float4 h2 = __ldg(&Hv[(size_t)b.x * L + lane]);
        float4 h3 = __ldg(&Hv[(size_t)b.z * L + lane]);
        float n0 = __int_as_float(a.y), n1 = __int_as_float(a.w);
        float n2 = __int_as_float(b.y), n3 = __int_as_float(b.w);
        acc.x = fmaf(h3.x, n3, fmaf(h2.x, n2, fmaf(h1.x, n1, fmaf(h0.x, n0, acc.x))));
        acc.y = fmaf(h3.y, n3, fmaf(h2.y, n2, fmaf(h1.y, n1, fmaf(h0.y, n0, acc.y))));
        acc.z = fmaf(h3.z, n3, fmaf(h2.z, n2, fmaf(h1.z, n1, fmaf(h0.z, n0, acc.z))));
        acc.w = fmaf(h3.w, n3, fmaf(h2.w, n2, fmaf(h1.w, n1, fmaf(h0.w, n0, acc.w))));
    }
    float ds = g_dis[node];
    float sw = ds * ds;
    float4 hs = __ldg(&Hv[(size_t)node * L + lane]);
    acc.x = fmaf(hs.x, sw, acc.x);
    acc.y = fmaf(hs.y, sw, acc.y);
    acc.z = fmaf(hs.z, sw, acc.z);
    acc.w = fmaf(hs.w, sw, acc.w);
    return acc;
}

// ---------------------------------------------------------------------------
__global__ void __launch_bounds__(TPB, 5) k_mega(
        const float* __restrict__ x, const void* __restrict__ ei,
        const float* __restrict__ W1, const float* __restrict__ b1,
        const float* __restrict__ W2, const float* __restrict__ b2,
        const float* __restrict__ W3, const float* __restrict__ b3,
        float* __restrict__ out, int N, int E) {
    __shared__ SM sm;
    int gtid = blockIdx.x * TPB + threadIdx.x;

    // dtype detect (cheap, block 0 warp 0)
    if (blockIdx.x == 0 && threadIdx.x < 32) {
        const long long* p = (const long long*)ei;
        long long v0 = p[threadIdx.x], v1 = p[32 + threadIdx.x];
        int ok = (v0 >= 0 && v0 < (long long)N && v1 >= 0 && v1 < (long long)N);
        unsigned m = __ballot_sync(0xffffffffu, ok);
        if (threadIdx.x == 0) g_is64 = (m == 0xffffffffu);
    }

    // Phase A: GEMM1 (independent) then degree histogram (deg pre-zeroed)
    gemm_phase<64, 64>(x, W1, g_h, N, &sm);
    {
        // need is64 visible: block0 wrote it before its gemm; other blocks
        // must not read until barrier... read AFTER gsync below? degree needs
        // it. Safe path: every block re-derives locally (cheap, 2 loads).
        const long long* p = (const long long*)ei;
        int is64l;
        {
            long long v0 = p[0], v1 = p[1];
            // heuristic identical to global detect but evaluated per block on
            // 64 values to stay deterministic with the global one:
            int ok = 1;
            for (int j = 0; j < 64; j++) {
                long long v = p[j];
                if (v < 0 || v >= (long long)N) { ok = 0; break; }
            }
            is64l = ok;
            (void)v0; (void)v1;
        }
        for (int e = gtid; e < E; e += NTH)
            atomicAdd(&g_deg[edge_at(ei, (size_t)E + e, is64l)], 1);
    }
    gsync(1u * NB);
    int is64 = g_is64;

    // Phase B: bump-allocate padded rowptr + dis + write pad slots
    for (int i = gtid; i < N; i += NTH) {
        int d = g_deg[i];
        int pad = (d + 3) & ~3;
        int st = atomicAdd(&g_alloc, pad);
        g_rowptr[i] = st;
        g_dis[i] = rsqrtf((float)(d + 1));
        for (int j = d; j < pad; j++) g_csr[st + j] = make_int2(0, 0);
    }
    gsync(2u * NB);

    // Phase C: fill CSR
    for (int e = gtid; e < E; e += NTH) {
        int s = edge_at(ei, e, is64);
        int d = edge_at(ei, (size_t)E + e, is64);
        int pos = atomicAdd(&g_cursor[d], 1);
        g_csr[g_rowptr[d] + pos] = make_int2(s, __float_as_int(g_dis[s] * g_dis[d]));
    }
    gsync(3u * NB);

    // Phase D: gather1 (h1 -> tanh -> o1), also re-zero cursor for next run
    for (int i = gtid; i < N; i += NTH) g_cursor[i] = 0;
    {
        const float4* Hv = (const float4*)g_h;
        const float4* bv4 = (const float4*)b1;
        long long items = (long long)N * 16;
        for (long long it = gtid; it < items; it += NTH) {
            int node = (int)(it >> 4);
            int lane = (int)(it & 15);
            float4 acc = gather_acc<16>(Hv, node, lane);
            float4 bv = __ldg(&bv4[lane]);
            acc.x = fast_tanh(acc.x + bv.x);
            acc.y = fast_tanh(acc.y + bv.y);
            acc.z = fast_tanh(acc.z + bv.z);
            acc.w = fast_tanh(acc.w + bv.w);
            ((float4*)g_o)[(size_t)node * 16 + lane] = acc;
        }
    }
    gsync(4u * NB);

    // Phase E: GEMM2 (o1 @ W2 -> h2)
    gemm_phase<64, 32>(g_o, W2, g_h, N, &sm);
    gsync(5u * NB);

    // Phase F: gather2 + tanh + fused projection (o2 . W3) -> g_o[node]
    {
        const float4* Hv = (const float4*)g_h;
        const float4* bv4 = (const float4*)b2;
        const float4* w34 = (const float4*)W3;
        int lane = threadIdx.x & 31;
        int lane8 = lane & 7;
        long long items = (long long)N * 8;
        long long chunks = (items + 31) >> 5;
        long long gw = gtid >> 5;
        long long warps = (long long)NTH >> 5;
        float4 w3 = __ldg(&w34[lane8]);
        for (long long c = gw; c < chunks; c += warps) {
            long long it = (c << 5) + lane;
            bool act = it < items;
            float partial = 0.f;
            int node = 0;
            if (act) {
                node = (int)(it >> 3);
                int l = (int)(it & 7);
                float4 acc = gather_acc<8>(Hv, node, l);
                float4 bv = __ldg(&bv4[l]);
                acc.x = fast_tanh(acc.x + bv.x);
                acc.y = fast_tanh(acc.y + bv.y);
                acc.z = fast_tanh(acc.z + bv.z);
                acc.w = fast_tanh(acc.w + bv.w);
                partial = acc.x * w3.x + acc.y * w3.y + acc.z * w3.z + acc.w * w3.w;
            }
            partial += __shfl_down_sync(0xffffffffu, partial, 4, 8);
            partial += __shfl_down_sync(0xffffffffu, partial, 2, 8);
            partial += __shfl_down_sync(0xffffffffu, partial, 1, 8);
            if (act && lane8 == 0) g_o[node] = partial;
        }
    }
    gsync(6u * NB);

    // Phase G: final scalar gather (one warp per node); zero deg after use
    {
        float bb = __ldg(b3);
        int wg = gtid >> 5;
        int lane = threadIdx.x & 31;
        for (int n = wg; n < N; n += (NTH >> 5)) {
            int start = g_rowptr[n];
            int c = g_deg[n];
            float acc = 0.f;
            for (int j = lane; j < c; j += 32) {
                int2 p = __ldg(&g_csr[start + j]);
                acc = fmaf(__ldg(&g_o[p.x]), __int_as_float(p.y), acc);
            }
            #pragma unroll
            for (int off = 16; off; off >>= 1)
                acc += __shfl_down_sync(0xffffffffu, acc, off);
            if (lane == 0) {
                float ds = g_dis[n];
                out[n] = fmaf(g_o[n], ds * ds, acc) + bb;
                g_deg[n] = 0;                    // restore invariant
            }
        }
    }

    // final arrival: last CTA resets counters for the next graph replay
    __syncthreads();
    if (threadIdx.x == 0) {
        __threadfence();
        unsigned v = atomicAdd(&g_bar, 1u);
        if (v == 7u * NB - 1u) { g_bar = 0u; g_alloc = 0; }
    }
}

// ---------------------------------------------------------------------------
extern "C" void kernel_launch(void* const* d_in, const int* in_sizes, int n_in,
                              void* d_out, int out_size) {
    const float* x  = (const float*)d_in[0];
    const void*  ei = d_in[1];
    const float* W1 = (const float*)d_in[2];
    const float* b1 = (const float*)d_in[3];
    const float* W2 = (const float*)d_in[4];
    const float* b2 = (const float*)d_in[5];
    const float* W3 = (const float*)d_in[6];
    const float* b3 = (const float*)d_in[7];
    float* out = (float*)d_out;

    int N = in_sizes[0] / 64;
    int E = in_sizes[1] / 2;

    k_mega<<<NB, TPB>>>(x, ei, W1, b1, W2, b2, W3, b3, out, N, E);
}

// round 6
// speedup vs baseline: 27.1002x; 1.1109x over previous
#include <cuda_runtime.h>

// ---------------------------------------------------------------------------
// 3-layer GCN persistent megakernel, round 6:
//  - pre-scaled features (hs = dis*h folded into GEMM epilogue): CSR entries
//    are 4B src-only, gather is pure adds, fill has no dis lookups
//  - pads point at the node itself; epilogue corrects with (1 - padcnt)
//  - dynamic (work-stealing) tile scheduling for both GEMMs
//  - deferred zeroing of counters across graph replays
// ---------------------------------------------------------------------------

#define NMAX 100000
#define EMAX 1600000
#define CSRMAX (EMAX + 4 * NMAX)
#define NB  740          // 148 SMs x 5 CTAs
#define TPB 256
#define NTH (NB * TPB)

__device__ unsigned g_bar;        // zero-init; restored to 0 at exit
__device__ int   g_alloc;         // zero-init; restored at exit
__device__ int   g_work[8];       // GEMM tile counters; restored at exit
__device__ int   g_deg[NMAX];     // zeroed by previous run's final phase
__device__ int   g_rowptr[NMAX];
__device__ int   g_cursor[NMAX];  // zeroed by previous run's gather1 phase
__device__ float g_dis[NMAX];
__device__ __align__(16) int g_csr[CSRMAX];   // src indices; pads = dst itself
__device__ float g_h[(size_t)NMAX * 64];
__device__ float g_o[(size_t)NMAX * 64];

struct SM {
    __align__(16) float w[4096];
    int tile;
};

__device__ __forceinline__ float fast_tanh(float x) {
    float y;
    asm("tanh.approx.f32 %0, %1;" : "=f"(y) : "f"(x));
    return y;
}

__device__ __forceinline__ void gsync(unsigned target) {
    __syncthreads();
    if (threadIdx.x == 0) {
        __threadfence();
        atomicAdd(&g_bar, 1u);
        while (*((volatile unsigned*)&g_bar) < target) __nanosleep(64);
    }
    __syncthreads();
}

__device__ __forceinline__ int edge_at(const void* ei, size_t idx, int is64) {
    if (is64) return (int)((const long long*)ei)[idx];
    return ((const int*)ei)[idx];
}

// ---- GEMM: O[N,M] = dis[row] * (X[N,K] @ W[K,M]), dynamic tiles ------------
template <int K, int M>
__device__ void gemm_phase(const float* __restrict__ X, const float* __restrict__ W,
                           float* __restrict__ O, int N, SM* sm, int workid) {
    constexpr int TN = M / 16;
    for (int i = threadIdx.x; i < K * M; i += TPB) sm->w[i] = W[i];
    int cg = threadIdx.x & 15;
    int rg = threadIdx.x >> 4;
    int tiles = (N + 63) >> 6;
    const float4* __restrict__ X4 = (const float4*)X;
    for (;;) {
        __syncthreads();
        if (threadIdx.x == 0) sm->tile = atomicAdd(&g_work[workid], 1);
        __syncthreads();
        int tile = sm->tile;
        if (tile >= tiles) break;
        int row0 = tile * 64 + rg * 4;
        bool full = (row0 + 3 < N);
        float acc[4][TN];
        #pragma unroll
        for (int r = 0; r < 4; r++)
            #pragma unroll
            for (int t = 0; t < TN; t++) acc[r][t] = 0.f;
        #pragma unroll 2
        for (int k4 = 0; k4 < K / 4; k4++) {
            float4 xv[4];
            #pragma unroll
            for (int r = 0; r < 4; r++) {
                int row = row0 + r;
                if (full || row < N) xv[r] = __ldg(&X4[(size_t)row * (K / 4) + k4]);
                else xv[r] = make_float4(0.f, 0.f, 0.f, 0.f);
            }
            #pragma unroll
            for (int kk = 0; kk < 4; kk++) {
                int k = k4 * 4 + kk;
                float wv[TN];
                if (TN == 4) {
                    float4 wq = ((const float4*)sm->w)[k * (M / 4) + cg];
                    wv[0] = wq.x; wv[1] = wq.y; wv[2] = wq.z; wv[3] = wq.w;
                } else {
                    float2 wq = ((const float2*)sm->w)[k * (M / 2) + cg];
                    wv[0] = wq.x; wv[1] = wq.y;
                }
                float xs[4] = { kk == 0 ? xv[0].x : kk == 1 ? xv[0].y : kk == 2 ? xv[0].z : xv[0].w,
                                kk == 0 ? xv[1].x : kk == 1 ? xv[1].y : kk == 2 ? xv[1].z : xv[1].w,
                                kk == 0 ? xv[2].x : kk == 1 ? xv[2].y : kk == 2 ? xv[2].z : xv[2].w,
                                kk == 0 ? xv[3].x : kk == 1 ? xv[3].y : kk == 2 ? xv[3].z : xv[3].w };
                #pragma unroll
                for (int t = 0; t < TN; t++)
                    #pragma unroll
                    for (int r = 0; r < 4; r++)
                        acc[r][t] = fmaf(xs[r], wv[t], acc[r][t]);
            }
        }
        #pragma unroll
        for (int r = 0; r < 4; r++) {
            int row = row0 + r;
            if (row < N) {
                float dsr = g_dis[row];
                #pragma unroll
                for (int t = 0; t < TN; t++)
                    O[(size_t)row * M + cg * TN + t] = acc[r][t] * dsr;
            }
        }
    }
}

// ---- gather core: plain sum of pre-scaled features -------------------------
template <int L>
__device__ __forceinline__ float4 gather_sum(const float4* __restrict__ Hv,
                                             const int4* __restrict__ C4,
                                             int pc, int lane) {
    float4 acc = make_float4(0.f, 0.f, 0.f, 0.f);
    for (int j = 0; j < pc; j++) {
        int4 a = __ldg(&C4[j]);
        float4 h0 = __ldg(&Hv[(size_t)a.x * L + lane]);
        float4 h1 = __ldg(&Hv[(size_t)a.y * L + lane]);
        float4 h2 = __ldg(&Hv[(size_t)a.z * L + lane]);
        float4 h3 = __ldg(&Hv[(size_t)a.w * L + lane]);
        acc.x += (h0.x + h1.x) + (h2.x + h3.x);
        acc.y += (h0.y + h1.y) + (h2.y + h3.y);
        acc.z += (h0.z + h1.z) + (h2.z + h3.z);
        acc.w += (h0.w + h1.w) + (h2.w + h3.w);
    }
    return acc;
}

// ---------------------------------------------------------------------------
__global__ void __launch_bounds__(TPB, 5) k_mega(
        const float* __restrict__ x, const void* __restrict__ ei,
        const float* __restrict__ W1, const float* __restrict__ b1,
        const float* __restrict__ W2, const float* __restrict__ b2,
        const float* __restrict__ W3, const float* __restrict__ b3,
        float* __restrict__ out, int N, int E) {
    __shared__ SM sm;
    int gtid = blockIdx.x * TPB + threadIdx.x;

    // local dtype detect (every block derives the same answer)
    int is64;
    {
        const long long* p = (const long long*)ei;
        int ok = 1;
        for (int j = 0; j < 64; j++) {
            long long v = p[j];
            if (v < 0 || v >= (long long)N) { ok = 0; break; }
        }
        is64 = ok;
    }

    // Phase A: degree histogram (deg pre-zeroed by previous run)
    for (int e = gtid; e < E; e += NTH)
        atomicAdd(&g_deg[edge_at(ei, (size_t)E + e, is64)], 1);
    gsync(1u * NB);

    // Phase B: bump-allocate padded rowptr + dis + write pad entries (= self)
    for (int i = gtid; i < N; i += NTH) {
        int d = g_deg[i];
        int pad = (d + 3) & ~3;
        int st = atomicAdd(&g_alloc, pad);
        g_rowptr[i] = st;
        g_dis[i] = rsqrtf((float)(d + 1));
        for (int j = d; j < pad; j++) g_csr[st + j] = i;
    }
    gsync(2u * NB);

    // Phase C: GEMM1 (x @ W1, scaled by dis) + CSR fill (independent work)
    gemm_phase<64, 64>(x, W1, g_h, N, &sm, 0);
    for (int e = gtid; e < E; e += NTH) {
        int s = edge_at(ei, e, is64);
        int d = edge_at(ei, (size_t)E + e, is64);
        int pos = atomicAdd(&g_cursor[d], 1);
        g_csr[g_rowptr[d] + pos] = s;
    }
    gsync(3u * NB);

    // Phase D: gather1 -> o1 = tanh(dis*(sum + (1-pad)*hs_self) + b1); zero cursor
    for (int i = gtid; i < N; i += NTH) g_cursor[i] = 0;
    {
        const float4* Hv = (const float4*)g_h;
        const float4* bv4 = (const float4*)b1;
        long long items = (long long)N * 16;
        for (long long it = gtid; it < items; it += NTH) {
            int node = (int)(it >> 4);
            int lane = (int)(it & 15);
            int d = g_deg[node];
            int pc = (d + 3) >> 2;
            float coef = 1.0f - (float)((pc << 2) - d);
            float4 acc = gather_sum<16>(Hv, (const int4*)(g_csr + g_rowptr[node]), pc, lane);
            float4 hs = __ldg(&Hv[(size_t)node * 16 + lane]);
            acc.x = fmaf(hs.x, coef, acc.x);
            acc.y = fmaf(hs.y, coef, acc.y);
            acc.z = fmaf(hs.z, coef, acc.z);
            acc.w = fmaf(hs.w, coef, acc.w);
            float dsn = g_dis[node];
            float4 bv = __ldg(&bv4[lane]);
            float4 o;
            o.x = fast_tanh(fmaf(acc.x, dsn, bv.x));
            o.y = fast_tanh(fmaf(acc.y, dsn, bv.y));
            o.z = fast_tanh(fmaf(acc.z, dsn, bv.z));
            o.w = fast_tanh(fmaf(acc.w, dsn, bv.w));
            ((float4*)g_o)[(size_t)node * 16 + lane] = o;
        }
    }
    gsync(4u * NB);

    // Phase E: GEMM2 (o1 @ W2, scaled by dis) -> g_h
    gemm_phase<64, 32>(g_o, W2, g_h, N, &sm, 1);
    gsync(5u * NB);

    // Phase F: gather2 + tanh + fused projection; store hs3 = dis*(o2.W3)
    {
        const float4* Hv = (const float4*)g_h;
        const float4* bv4 = (const float4*)b2;
        const float4* w34 = (const float4*)W3;
        int lane = threadIdx.x & 31;
        int lane8 = lane & 7;
        long long items = (long long)N * 8;
        long long chunks = (items + 31) >> 5;
        long long gw = gtid >> 5;
        long long warps = (long long)NTH >> 5;
        float4 w3 = __ldg(&w34[lane8]);
        for (long long c = gw; c < chunks; c += warps) {
            long long it = (c << 5) + lane;
            bool act = it < items;
            float partial = 0.f;
            int node = 0;
            float dsn = 0.f;
            if (act) {
                node = (int)(it >> 3);
                int l = (int)(it & 7);
                int d = g_deg[node];
                int pc = (d + 3) >> 2;
                float coef = 1.0f - (float)((pc << 2) - d);
                float4 acc = gather_sum<8>(Hv, (const int4*)(g_csr + g_rowptr[node]), pc, l);
                float4 hs = __ldg(&Hv[(size_t)node * 8 + l]);
                acc.x = fmaf(hs.x, coef, acc.x);
                acc.y = fmaf(hs.y, coef, acc.y);
                acc.z = fmaf(hs.z, coef, acc.z);
                acc.w = fmaf(hs.w, coef, acc.w);
                dsn = g_dis[node];
                float4 bv = __ldg(&bv4[l]);
                float4 o;
                o.x = fast_tanh(fmaf(acc.x, dsn, bv.x));
                o.y = fast_tanh(fmaf(acc.y, dsn, bv.y));
                o.z = fast_tanh(fmaf(acc.z, dsn, bv.z));
                o.w = fast_tanh(fmaf(acc.w, dsn, bv.w));
                partial = o.x * w3.x + o.y * w3.y + o.z * w3.z + o.w * w3.w;
            }
            partial += __shfl_down_sync(0xffffffffu, partial, 4, 8);
            partial += __shfl_down_sync(0xffffffffu, partial, 2, 8);
            partial += __shfl_down_sync(0xffffffffu, partial, 1, 8);
            if (act && lane8 == 0) g_o[node] = dsn * partial;
        }
    }
    gsync(6u * NB);

    // Phase G: scalar gather3; out = dis*(sum + hs3_self) + b3; zero deg
    {
        float bb = __ldg(b3);
        int wg = gtid >> 5;
        int lane = threadIdx.x & 31;
        for (int n = wg; n < N; n += (NTH >> 5)) {
            int start = g_rowptr[n];
            int c = g_deg[n];
            float acc = 0.f;
            for (int j = lane; j < c; j += 32)
                acc += __ldg(&g_o[g_csr[start + j]]);
            #pragma unroll
            for (int off = 16; off; off >>= 1)
                acc += __shfl_down_sync(0xffffffffu, acc, off);
            if (lane == 0) {
                out[n] = fmaf(g_dis[n], acc + g_o[n], bb);
                g_deg[n] = 0;                    // restore invariant
            }
        }
    }

    // final arrival: last CTA resets counters for next graph replay
    __syncthreads();
    if (threadIdx.x == 0) {
        __threadfence();
        unsigned v = atomicAdd(&g_bar, 1u);
        if (v == 7u * NB - 1u) {
            g_bar = 0u; g_alloc = 0; g_work[0] = 0; g_work[1] = 0;
        }
    }
}

// ---------------------------------------------------------------------------
extern "C" void kernel_launch(void* const* d_in, const int* in_sizes, int n_in,
                              void* d_out, int out_size) {
    const float* x  = (const float*)d_in[0];
    const void*  ei = d_in[1];
    const float* W1 = (const float*)d_in[2];
    const float* b1 = (const float*)d_in[3];
    const float* W2 = (const float*)d_in[4];
    const float* b2 = (const float*)d_in[5];
    const float* W3 = (const float*)d_in[6];
    const float* b3 = (const float*)d_in[7];
    float* out = (float*)d_out;

    int N = in_sizes[0] / 64;
    int E = in_sizes[1] / 2;

    k_mega<<<NB, TPB>>>(x, ei, W1, b1, W2, b2, W3, b3, out, N, E);
}